// round 3
// baseline (speedup 1.0000x reference)
#include <cuda_runtime.h>
#include <cstdint>

// Problem constants (fixed shapes)
#define B        16
#define T        4096
#define D4       128          // float4 per embedding row (512 floats)
#define KN       1024         // max_nodes
#define KE       2048         // max_edges
#define NODE_ROWS_PER_B (KN * 2)   // 2048
#define EDGE_ROWS_PER_B (KE * 5)   // 10240
#define NODE_ROWS (B * NODE_ROWS_PER_B)  // 32768
#define NODE_SLOTS (B * KN)   // 16384
#define EDGE_SLOTS (B * KE)   // 32768
#define NODE_PAIRS (NODE_SLOTS / 2)      // 8192
#define EDGE_PAIRS (EDGE_SLOTS / 2)      // 16384
#define TOTAL_PAIRS (NODE_PAIRS + EDGE_PAIRS)  // 24576

// Scratch: compacted positions per batch (device globals, no allocation)
__device__ int g_node_pos[NODE_SLOTS];
__device__ int g_edge_pos[EDGE_SLOTS];

// ---------------------------------------------------------------------------
// Kernel 1: per-batch dual stream compaction (routing==0 -> nodes,
// routing==1 -> edges). One block per batch, 1024 threads, 4 elems/thread.
// Dual counts packed: zeros in bits [0:16), ones in bits [16:32).
// ---------------------------------------------------------------------------
__global__ void compact_kernel(const int* __restrict__ routing) {
    const int b    = blockIdx.x;
    const int tid  = threadIdx.x;          // 0..1023
    const int lane = tid & 31;
    const int wid  = tid >> 5;

    // Reset scratch for determinism across graph replays.
    g_node_pos[b * KN + tid] = -1;
    g_edge_pos[b * KE + tid] = -1;
    g_edge_pos[b * KE + 1024 + tid] = -1;

    const int4 rv = reinterpret_cast<const int4*>(routing + (size_t)b * T)[tid];
    int v[4] = { rv.x, rv.y, rv.z, rv.w };

    int c0 = 0, c1 = 0;
#pragma unroll
    for (int i = 0; i < 4; i++) { c0 += (v[i] == 0); c1 += (v[i] == 1); }
    const int packed = c0 | (c1 << 16);

    // Warp inclusive scan
    int x = packed;
#pragma unroll
    for (int off = 1; off < 32; off <<= 1) {
        int y = __shfl_up_sync(0xffffffffu, x, off);
        if (lane >= off) x += y;
    }

    __shared__ int warp_sums[32];
    if (lane == 31) warp_sums[wid] = x;
    __syncthreads();

    if (wid == 0) {
        int w = warp_sums[lane];
#pragma unroll
        for (int off = 1; off < 32; off <<= 1) {
            int y = __shfl_up_sync(0xffffffffu, w, off);
            if (lane >= off) w += y;
        }
        warp_sums[lane] = w;
    }
    __syncthreads();

    const int incl = x + (wid > 0 ? warp_sums[wid - 1] : 0);
    const int excl = incl - packed;
    int idx0 = excl & 0xffff;
    int idx1 = excl >> 16;

    const int t0 = tid * 4;
#pragma unroll
    for (int i = 0; i < 4; i++) {
        const int val = v[i];
        if (val == 0) {
            if (idx0 < KN) g_node_pos[b * KN + idx0] = t0 + i;
            idx0++;
        } else if (val == 1) {
            if (idx1 < KE) g_edge_pos[b * KE + idx1] = t0 + i;
            idx1++;
        }
    }
}

// ---------------------------------------------------------------------------
// Kernel 2: gather, slot-PAIR per block for 2x load MLP and 4/10 outstanding
// streaming stores per thread. Destinations per block are fully contiguous
// (8KB node-pair, 20KB edge-pair). Pairs never straddle a batch boundary.
// Output layout: node_pe [B,2048,512] flat, then edge_pe [B,10240,512] flat.
// ---------------------------------------------------------------------------
__global__ void gather_kernel(const float4* __restrict__ pe,
                              float4* __restrict__ out) {
    const int pair = blockIdx.x;
    const int t = threadIdx.x;

    if (pair < NODE_PAIRS) {
        const int s0 = pair * 2;                 // first node slot
        int p0 = g_node_pos[s0];
        int p1 = g_node_pos[s0 + 1];
        if (p0 < 0) p0 = 0;
        if (p1 < 0) p1 = 0;
        const float4 v0 = __ldg(pe + (size_t)p0 * D4 + t);
        const float4 v1 = __ldg(pe + (size_t)p1 * D4 + t);
        // slot s -> output rows 2s, 2s+1 (global row index, node region)
        float4* dst = out + ((size_t)s0 * 2) * D4 + t;
        __stcs(dst,          v0);
        __stcs(dst + 1 * D4, v0);
        __stcs(dst + 2 * D4, v1);
        __stcs(dst + 3 * D4, v1);
    } else {
        const int s0 = (pair - NODE_PAIRS) * 2;  // first edge slot
        int p0 = g_edge_pos[s0];
        int p1 = g_edge_pos[s0 + 1];
        if (p0 < 0) p0 = 0;
        if (p1 < 0) p1 = 0;
        const float4 v0 = __ldg(pe + (size_t)p0 * D4 + t);
        const float4 v1 = __ldg(pe + (size_t)p1 * D4 + t);
        // edge slot s -> output rows NODE_ROWS + 5s .. +5s+4
        float4* dst = out + ((size_t)NODE_ROWS + (size_t)s0 * 5) * D4 + t;
        __stcs(dst,          v0);
        __stcs(dst + 1 * D4, v0);
        __stcs(dst + 2 * D4, v0);
        __stcs(dst + 3 * D4, v0);
        __stcs(dst + 4 * D4, v0);
        __stcs(dst + 5 * D4, v1);
        __stcs(dst + 6 * D4, v1);
        __stcs(dst + 7 * D4, v1);
        __stcs(dst + 8 * D4, v1);
        __stcs(dst + 9 * D4, v1);
    }
}

// ---------------------------------------------------------------------------
// Inputs (metadata order):
//   d_in[0] routing  (int32, B*T)
//   d_in[1] max_nodes (scalar, fixed 1024)
//   d_in[2] max_edges (scalar, fixed 2048)
//   d_in[3] pos_embed (float32, T*512)
// d_out: float32, node_pe then edge_pe, flat.
// ---------------------------------------------------------------------------
extern "C" void kernel_launch(void* const* d_in, const int* in_sizes, int n_in,
                              void* d_out, int out_size) {
    const int*    routing = (const int*)d_in[0];
    const float4* pe      = (const float4*)d_in[3];
    float4*       out     = (float4*)d_out;

    compact_kernel<<<B, 1024>>>(routing);
    gather_kernel<<<TOTAL_PAIRS, 128>>>(pe, out);
}